// round 5
// baseline (speedup 1.0000x reference)
#include <cuda_runtime.h>
#include <cuda_bf16.h>

#define NN 4096
#define DD 512
#define NCLS 64

__device__ int   g_tgt[NN];
__device__ float g_sq[NN];
__device__ float g_negsum[NN];
__device__ float g_loss;

// ---------------------------------------------------------------------------
// K-1: normalize targets to int32 regardless of stored dtype (int32 or int64).
// int64 detection: values are 0..63 (nonnegative), so the int32 view of an
// int64 buffer has every odd word == 0. Probability of a false positive with
// 2048 random int32 labels in 0..63 is ~0.
// ---------------------------------------------------------------------------
__global__ __launch_bounds__(1024) void k_cvt(const int* __restrict__ t) {
    __shared__ int any_odd;
    int tid = threadIdx.x;
    if (tid == 0) any_odd = 0;
    __syncthreads();
    int local = 0;
    for (int i = tid; i < NN / 2; i += 1024)
        local |= t[2 * i + 1];            // stays within first 16 KB either way
    if (local) atomicOr(&any_odd, 1);
    __syncthreads();
    bool is64 = (any_odd == 0);
    for (int i = tid; i < NN; i += 1024)
        g_tgt[i] = is64 ? t[2 * i] : t[i];
}

// ---------------------------------------------------------------------------
// K0: row squared norms + zero accumulators (graph-replay deterministic)
// ---------------------------------------------------------------------------
__global__ __launch_bounds__(256) void k_sq(const float* __restrict__ X) {
    int warp = threadIdx.x >> 5, lane = threadIdx.x & 31;
    int row = blockIdx.x * 8 + warp;
    const float4* xr = (const float4*)(X + (size_t)row * DD);
    float s = 0.f;
#pragma unroll
    for (int q = 0; q < 4; q++) {
        float4 v = xr[lane + q * 32];
        s += v.x * v.x + v.y * v.y + v.z * v.z + v.w * v.w;
    }
#pragma unroll
    for (int o = 16; o; o >>= 1) s += __shfl_xor_sync(0xffffffffu, s, o);
    if (lane == 0) { g_sq[row] = s; g_negsum[row] = 0.f; }
    if (blockIdx.x == 0 && threadIdx.x == 0) g_loss = 0.f;
}

// ---------------------------------------------------------------------------
// K1: tiled fp32 "SGEMM" X*X^T fused with dist + masked exp row-sums.
// 128x128 tile per block, 256 threads, 8x8 microtile, BK=16.
// ---------------------------------------------------------------------------
#define BM 128
#define BN 128
#define BK 16
#define TM 8
#define TN 8

__global__ __launch_bounds__(256) void k_gemm_negsum(const float* __restrict__ X)
{
    __shared__ float As[BK][BM + 4];
    __shared__ float Bs[BK][BN + 4];
    __shared__ float rowsum[BM];
    __shared__ int   tR[BM], tC[BN];
    __shared__ float sqR[BM], sqC[BN];

    const int tid = threadIdx.x;
    const int tx = tid & 15, ty = tid >> 4;
    const int m0 = blockIdx.y * BM, n0 = blockIdx.x * BN;

    for (int t = tid; t < BM; t += 256) {
        tR[t] = g_tgt[m0 + t];
        tC[t] = g_tgt[n0 + t];
        sqR[t] = g_sq[m0 + t];
        sqC[t] = g_sq[n0 + t];
        rowsum[t] = 0.f;
    }

    float acc[TM][TN];
#pragma unroll
    for (int a = 0; a < TM; a++)
#pragma unroll
        for (int b = 0; b < TN; b++) acc[a][b] = 0.f;

    for (int k0 = 0; k0 < DD; k0 += BK) {
        // load 128x16 A and B tiles, transposed into smem
#pragma unroll
        for (int i = 0; i < 2; i++) {
            int f = tid + i * 256;          // 0..511
            int row = f >> 2;
            int kc = (f & 3) * 4;
            float4 v = *(const float4*)&X[(size_t)(m0 + row) * DD + k0 + kc];
            As[kc + 0][row] = v.x; As[kc + 1][row] = v.y;
            As[kc + 2][row] = v.z; As[kc + 3][row] = v.w;
            float4 w = *(const float4*)&X[(size_t)(n0 + row) * DD + k0 + kc];
            Bs[kc + 0][row] = w.x; Bs[kc + 1][row] = w.y;
            Bs[kc + 2][row] = w.z; Bs[kc + 3][row] = w.w;
        }
        __syncthreads();

#pragma unroll
        for (int k = 0; k < BK; k++) {
            float4 a0 = *(const float4*)&As[k][ty * TM];
            float4 a1 = *(const float4*)&As[k][ty * TM + 4];
            float4 b0 = *(const float4*)&Bs[k][tx * TN];
            float4 b1 = *(const float4*)&Bs[k][tx * TN + 4];
            float av[TM] = {a0.x, a0.y, a0.z, a0.w, a1.x, a1.y, a1.z, a1.w};
            float bv[TN] = {b0.x, b0.y, b0.z, b0.w, b1.x, b1.y, b1.z, b1.w};
#pragma unroll
            for (int a = 0; a < TM; a++)
#pragma unroll
                for (int b = 0; b < TN; b++) acc[a][b] = fmaf(av[a], bv[b], acc[a][b]);
        }
        __syncthreads();
    }

    // epilogue: dist + masked exp(1-dist), per-row partial sums
#pragma unroll
    for (int a = 0; a < TM; a++) {
        int r = ty * TM + a;
        int trg = tR[r];
        float si = sqR[r];
        float rs = 0.f;
#pragma unroll
        for (int b = 0; b < TN; b++) {
            int c = tx * TN + b;
            if (trg != tC[c]) {
                float d2 = fmaxf(si + sqC[c] - 2.f * acc[a][b], 0.f);
                rs += __expf(1.0f - sqrtf(d2));
            }
        }
        atomicAdd(&rowsum[r], rs);
    }
    __syncthreads();
    for (int t = tid; t < BM; t += 256)
        atomicAdd(&g_negsum[m0 + t], rowsum[t]);
}

// ---------------------------------------------------------------------------
// K2: positive-pair loss. One block per row i; list same-class j>i; warp/pair
// dot-product recompute (no 64MB dist matrix).
// ---------------------------------------------------------------------------
__global__ __launch_bounds__(256) void k_pairs(const float* __restrict__ X)
{
    const int i = blockIdx.x;
    __shared__ float xi[DD];
    __shared__ int lst[NN];
    __shared__ int cnt;
    __shared__ float wacc[8];

    int tid = threadIdx.x;
    if (tid == 0) cnt = 0;
    for (int t = tid; t < DD / 4; t += 256)
        ((float4*)xi)[t] = ((const float4*)(X + (size_t)i * DD))[t];
    __syncthreads();

    int ti = g_tgt[i];
    for (int j = i + 1 + tid; j < NN; j += 256) {
        if (g_tgt[j] == ti) {
            int p = atomicAdd(&cnt, 1);
            lst[p] = j;
        }
    }
    __syncthreads();

    int nc = cnt;
    float si = g_sq[i];
    float nsi = g_negsum[i];
    int warp = tid >> 5, lane = tid & 31;
    float acc = 0.f;

    for (int p = warp; p < nc; p += 8) {
        int j = lst[p];
        const float4* xj = (const float4*)(X + (size_t)j * DD);
        const float4* xi4 = (const float4*)xi;
        float dot = 0.f;
#pragma unroll
        for (int q = 0; q < 4; q++) {
            float4 a = xi4[lane + q * 32];
            float4 b = xj[lane + q * 32];
            dot += a.x * b.x + a.y * b.y + a.z * b.z + a.w * b.w;
        }
#pragma unroll
        for (int o = 16; o; o >>= 1) dot += __shfl_xor_sync(0xffffffffu, dot, o);
        if (lane == 0) {
            float d2 = fmaxf(si + g_sq[j] - 2.f * dot, 0.f);
            float dist = sqrtf(d2);
            float J = logf(nsi + g_negsum[j]) + dist;
            float h = fmaxf(J, 0.f);
            acc += h * h;
        }
    }
    if (lane == 0) wacc[warp] = acc;
    __syncthreads();
    if (tid == 0) {
        float s = 0.f;
#pragma unroll
        for (int w = 0; w < 8; w++) s += wacc[w];
        if (s != 0.f) atomicAdd(&g_loss, s);
    }
}

// ---------------------------------------------------------------------------
// K3: finalize — class histogram -> len_p, out = loss / len_p
// ---------------------------------------------------------------------------
__global__ __launch_bounds__(256) void k_final(float* __restrict__ out)
{
    __shared__ int cnts[NCLS];
    int tid = threadIdx.x;
    if (tid < NCLS) cnts[tid] = 0;
    __syncthreads();
    for (int t = tid; t < NN; t += 256)
        atomicAdd(&cnts[g_tgt[t]], 1);
    __syncthreads();
    if (tid == 0) {
        float lp = 0.f;
#pragma unroll
        for (int c = 0; c < NCLS; c++) {
            float cc = (float)cnts[c];
            lp += cc * (cc - 1.f);
        }
        out[0] = g_loss / lp;
    }
}

// ---------------------------------------------------------------------------
extern "C" void kernel_launch(void* const* d_in, const int* in_sizes, int n_in,
                              void* d_out, int out_size) {
    // Bind by element count (inputs: NN*DD elements, targets: NN) — order-proof.
    const void* Xp;
    const void* Tp;
    if (in_sizes[0] == NN * DD) { Xp = d_in[0]; Tp = d_in[1]; }
    else                        { Xp = d_in[1]; Tp = d_in[0]; }
    const float* X = (const float*)Xp;
    float* out = (float*)d_out;

    k_cvt<<<1, 1024>>>((const int*)Tp);   // dtype-proof target normalize
    k_sq<<<NN / 8, 256>>>(X);
    dim3 grid(NN / BN, NN / BM);
    k_gemm_negsum<<<grid, 256>>>(X);
    k_pairs<<<NN, 256>>>(X);
    k_final<<<1, 256>>>(out);
}

// round 8
// speedup vs baseline: 3.2686x; 3.2686x over previous
#include <cuda_runtime.h>
#include <cuda_bf16.h>
#include <cstdint>

#define NN 4096
#define DD 512
#define NCLS 64
#define CMAX 160
#define NTRI 528            // 32*33/2 upper-tri 128x128 tiles

// ---------------- device globals (scratch; no runtime alloc) ----------------
__device__ int   g_tgt[NN];
__device__ int   g_rank[NN];
__device__ int   g_members[NCLS * CMAX];
__device__ int   g_count[NCLS];
__device__ float g_sq[NN];
__device__ float g_negsum[NN];
__device__ float g_loss;
__device__ float g_pd[NCLS * CMAX * CMAX];   // dist for same-class pairs (ri<rj)
__device__ uint4 g_hi4[NN * DD / 8];         // bf16 hi split, row-major (64 uint4/row)
__device__ uint4 g_lo4[NN * DD / 8];         // bf16 lo split

// ---------------- PTX helpers ----------------
__device__ __forceinline__ uint32_t s2u(const void* p) {
    uint32_t a;
    asm("{ .reg .u64 t; cvta.to.shared.u64 t, %1; cvt.u32.u64 %0, t; }"
        : "=r"(a) : "l"(p));
    return a;
}
__device__ __forceinline__ void cp16(uint32_t saddr, const void* g) {
    asm volatile("cp.async.cg.shared.global [%0], [%1], 16;" :: "r"(saddr), "l"(g));
}
#define CP_COMMIT() asm volatile("cp.async.commit_group;" ::: "memory")
#define CP_WAIT0()  asm volatile("cp.async.wait_group 0;" ::: "memory")

__device__ __forceinline__ void ldm_x4(uint32_t& r0, uint32_t& r1, uint32_t& r2,
                                       uint32_t& r3, uint32_t a) {
    asm volatile("ldmatrix.sync.aligned.m8n8.x4.shared.b16 {%0,%1,%2,%3}, [%4];"
                 : "=r"(r0), "=r"(r1), "=r"(r2), "=r"(r3) : "r"(a));
}
__device__ __forceinline__ void mma16816(float* d, const uint32_t* a, const uint32_t* b) {
    asm volatile(
        "mma.sync.aligned.m16n8k16.row.col.f32.bf16.bf16.f32 "
        "{%0,%1,%2,%3}, {%4,%5,%6,%7}, {%8,%9}, {%0,%1,%2,%3};"
        : "+f"(d[0]), "+f"(d[1]), "+f"(d[2]), "+f"(d[3])
        : "r"(a[0]), "r"(a[1]), "r"(a[2]), "r"(a[3]), "r"(b[0]), "r"(b[1]));
}

// ---------------- fast math (no MUFU on hot path) ----------------
__device__ __forceinline__ float fast_dist(float d2) {
    float y = __int_as_float(0x5f3759dfu - (__float_as_uint(d2) >> 1));
    y = y * fmaf(-0.5f * d2, y * y, 1.5f);
    y = y * fmaf(-0.5f * d2, y * y, 1.5f);
    y = y * fmaf(-0.5f * d2, y * y, 1.5f);
    return d2 > 1e-18f ? d2 * y : 0.0f;
}
__device__ __forceinline__ float exp1m(float dist) {  // exp(1 - dist)
    float t = (1.0f - dist) * 1.4426950408889634f;
    t = fmaxf(t, -125.0f);
    int n = __float2int_rn(t);
    float f = t - (float)n;
    float p = 1.3333558146e-3f;
    p = fmaf(p, f, 9.6181291076e-3f);
    p = fmaf(p, f, 5.5504108664e-2f);
    p = fmaf(p, f, 2.4022650696e-1f);
    p = fmaf(p, f, 6.9314718056e-1f);
    p = fmaf(p, f, 1.0f);
    return __int_as_float((uint32_t)(n + 127) << 23) * p;
}

// ---------------------------------------------------------------------------
// K-1: dtype-normalize targets (int32 or int64) + per-class rank/members
// ---------------------------------------------------------------------------
__global__ __launch_bounds__(1024) void k_cvt(const int* __restrict__ t) {
    __shared__ int any_odd;
    int tid = threadIdx.x;
    if (tid == 0) any_odd = 0;
    __syncthreads();
    int local = 0;
    for (int i = tid; i < NN / 2; i += 1024) local |= t[2 * i + 1];
    if (local) atomicOr(&any_odd, 1);
    __syncthreads();
    bool is64 = (any_odd == 0);
    for (int i = tid; i < NN; i += 1024) g_tgt[i] = is64 ? t[2 * i] : t[i];
    __syncthreads();
    int wid = tid >> 5, lane = tid & 31;
    for (int c = wid; c < NCLS; c += 32) {
        int cnt = 0;
        for (int base = 0; base < NN; base += 32) {
            int v = g_tgt[base + lane];
            unsigned m = __ballot_sync(0xffffffffu, v == c);
            if (v == c) {
                int r = cnt + __popc(m & ((1u << lane) - 1u));
                g_rank[base + lane] = r;
                if (r < CMAX) g_members[c * CMAX + r] = base + lane;
            }
            cnt += __popc(m);
        }
        if (lane == 0) g_count[c] = cnt;
    }
}

// ---------------------------------------------------------------------------
// K0: row norms + bf16 hi/lo split + zero accumulators
// ---------------------------------------------------------------------------
__global__ __launch_bounds__(256) void k_sq_split(const float* __restrict__ X) {
    int warp = threadIdx.x >> 5, lane = threadIdx.x & 31;
    int row = blockIdx.x * 8 + warp;
    const float4* xr = (const float4*)(X + (size_t)row * DD);
    uint2* hi2 = (uint2*)g_hi4;
    uint2* lo2 = (uint2*)g_lo4;
    float s = 0.f;
#pragma unroll
    for (int q = 0; q < 4; q++) {
        int i4 = lane + q * 32;
        float4 v = xr[i4];
        s += v.x * v.x + v.y * v.y + v.z * v.z + v.w * v.w;
        union { __nv_bfloat16 b[4]; uint2 u; } H, L;
        H.b[0] = __float2bfloat16(v.x); H.b[1] = __float2bfloat16(v.y);
        H.b[2] = __float2bfloat16(v.z); H.b[3] = __float2bfloat16(v.w);
        L.b[0] = __float2bfloat16(v.x - __bfloat162float(H.b[0]));
        L.b[1] = __float2bfloat16(v.y - __bfloat162float(H.b[1]));
        L.b[2] = __float2bfloat16(v.z - __bfloat162float(H.b[2]));
        L.b[3] = __float2bfloat16(v.w - __bfloat162float(H.b[3]));
        hi2[(size_t)row * 128 + i4] = H.u;
        lo2[(size_t)row * 128 + i4] = L.u;
    }
#pragma unroll
    for (int o = 16; o; o >>= 1) s += __shfl_xor_sync(0xffffffffu, s, o);
    if (lane == 0) { g_sq[row] = s; g_negsum[row] = 0.f; }
    if (blockIdx.x == 0 && threadIdx.x == 0) g_loss = 0.f;
}

// ---------------------------------------------------------------------------
// K1: split-bf16 symmetric GEMM via ldmatrix + mma.sync (HMMA), fused epilogue.
// 528 upper-tri 128x128 tiles, BK=64 double-buffered cp.async, 8 warps 32x64.
// ---------------------------------------------------------------------------
#define BUFSZ 16384               // one operand chunk: 128 rows x 128B
#define PHSZ  (4 * BUFSZ)         // Ahi,Alo,Bhi,Blo
#define SMEM_DYN (2 * PHSZ)       // double buffered: 128 KB

__device__ __forceinline__ void load_chunk(uint32_t dynb, int stage, int m0, int n0,
                                           int kq, int tid) {
#pragma unroll
    for (int op = 0; op < 4; op++) {
        const uint4* src = (op & 1) ? g_lo4 : g_hi4;
        int rb = (op < 2) ? m0 : n0;
        uint32_t dst = dynb + stage * PHSZ + op * BUFSZ;
#pragma unroll
        for (int u = 0; u < 4; u++) {
            int f = tid + u * 256;                 // 0..1023
            int r = f >> 3, c8 = f & 7;
            uint32_t bo = (uint32_t)(r * 128 + c8 * 16);
            cp16(dst + (bo ^ ((bo >> 3) & 0x70)),
                 &src[(size_t)(rb + r) * 64 + kq + c8]);
        }
    }
}

__global__ __launch_bounds__(256) void k_gemm_mma() {
    extern __shared__ __align__(1024) char dyn[];
    __shared__ int   tR[128], tC[128], rkR[128], rkC[128];
    __shared__ float sqR[128], sqC[128], rowsum[128], colsum[128];

    const int tid = threadIdx.x;
    const int lane = tid & 31;
    const int wid = tid >> 5;
    const int wm = wid & 3, wn = wid >> 2;
    const uint32_t dynb = s2u(dyn);

    // upper-tri tile decode: blk = bj*(bj+1)/2 + bi, bi<=bj
    int k = blockIdx.x;
    int bj = (int)((sqrtf(8.f * (float)k + 1.f) - 1.f) * 0.5f);
    while ((bj + 1) * (bj + 2) / 2 <= k) bj++;
    while (bj * (bj + 1) / 2 > k) bj--;
    int bi = k - bj * (bj + 1) / 2;
    const int m0 = bi * 128, n0 = bj * 128;
    const bool offdiag = (bi != bj);

    for (int t = tid; t < 128; t += 256) {
        tR[t] = g_tgt[m0 + t];   tC[t] = g_tgt[n0 + t];
        sqR[t] = g_sq[m0 + t];   sqC[t] = g_sq[n0 + t];
        rkR[t] = g_rank[m0 + t]; rkC[t] = g_rank[n0 + t];
        rowsum[t] = 0.f;         colsum[t] = 0.f;
    }

    float acc[2][8][4];
#pragma unroll
    for (int mi = 0; mi < 2; mi++)
#pragma unroll
        for (int nf = 0; nf < 8; nf++)
#pragma unroll
            for (int e = 0; e < 4; e++) acc[mi][nf][e] = 0.f;

    load_chunk(dynb, 0, m0, n0, 0, tid);
    CP_COMMIT(); CP_WAIT0();
    __syncthreads();

    const int mat = lane >> 3, rr = lane & 7;

    for (int ci = 0; ci < 8; ci++) {
        const int cur = ci & 1;
        if (ci < 7) { load_chunk(dynb, cur ^ 1, m0, n0, (ci + 1) * 8, tid); CP_COMMIT(); }

        const uint32_t Ah = dynb + cur * PHSZ;
        const uint32_t Al = Ah + BUFSZ;
        const uint32_t Bh = Ah + 2 * BUFSZ;
        const uint32_t Bl = Ah + 3 * BUFSZ;

#pragma unroll
        for (int ks = 0; ks < 4; ks++) {
            uint32_t ahi[2][4], alo[2][4];
#pragma unroll
            for (int mi = 0; mi < 2; mi++) {
                int row = wm * 32 + mi * 16 + (mat & 1) * 8 + rr;
                uint32_t bo = (uint32_t)(row * 128 + ks * 32 + (mat >> 1) * 16);
                uint32_t sw = bo ^ ((bo >> 3) & 0x70);
                ldm_x4(ahi[mi][0], ahi[mi][1], ahi[mi][2], ahi[mi][3], Ah + sw);
                ldm_x4(alo[mi][0], alo[mi][1], alo[mi][2], alo[mi][3], Al + sw);
            }
            uint32_t bhi[8][2], blo[8][2];
#pragma unroll
            for (int q = 0; q < 4; q++) {
                int row = wn * 64 + q * 16 + (mat >> 1) * 8 + rr;
                uint32_t bo = (uint32_t)(row * 128 + ks * 32 + (mat & 1) * 16);
                uint32_t sw = bo ^ ((bo >> 3) & 0x70);
                uint32_t r0, r1, r2, r3;
                ldm_x4(r0, r1, r2, r3, Bh + sw);
                bhi[2 * q][0] = r0; bhi[2 * q][1] = r1;
                bhi[2 * q + 1][0] = r2; bhi[2 * q + 1][1] = r3;
                ldm_x4(r0, r1, r2, r3, Bl + sw);
                blo[2 * q][0] = r0; blo[2 * q][1] = r1;
                blo[2 * q + 1][0] = r2; blo[2 * q + 1][1] = r3;
            }
#pragma unroll
            for (int mi = 0; mi < 2; mi++)
#pragma unroll
                for (int nf = 0; nf < 8; nf++) {
                    mma16816(acc[mi][nf], ahi[mi], bhi[nf]);
                    mma16816(acc[mi][nf], ahi[mi], blo[nf]);
                    mma16816(acc[mi][nf], alo[mi], bhi[nf]);
                }
        }
        if (ci < 7) CP_WAIT0();
        __syncthreads();
    }

    // ---- epilogue: dist, masked exp, row/col negsums, pos-pair dist store ----
    const int tq = lane >> 2, tr = lane & 3;
    float csum[8][2];
#pragma unroll
    for (int nf = 0; nf < 8; nf++) { csum[nf][0] = 0.f; csum[nf][1] = 0.f; }

#pragma unroll
    for (int mi = 0; mi < 2; mi++) {
#pragma unroll
        for (int h = 0; h < 2; h++) {
            int row = wm * 32 + mi * 16 + tq + h * 8;
            int ti = tR[row]; float si = sqR[row]; int ri = rkR[row];
            int gi = m0 + row;
            float rsum = 0.f;
#pragma unroll
            for (int nf = 0; nf < 8; nf++) {
#pragma unroll
                for (int p = 0; p < 2; p++) {
                    int col = wn * 64 + nf * 8 + tr * 2 + p;
                    float dot = acc[mi][nf][h * 2 + p];
                    float d2 = fmaxf(si + sqC[col] - 2.f * dot, 0.f);
                    float dist = fast_dist(d2);
                    bool same = (ti == tC[col]);
                    float ev = same ? 0.f : exp1m(dist);
                    rsum += ev;
                    csum[nf][p] += ev;
                    if (same) {
                        int gj = n0 + col;
                        if (gi < gj) {
                            int rj = rkC[col];
                            if (ri < CMAX && rj < CMAX)
                                g_pd[(ti * CMAX + ri) * CMAX + rj] = dist;
                        }
                    }
                }
            }
            rsum += __shfl_xor_sync(0xffffffffu, rsum, 1);
            rsum += __shfl_xor_sync(0xffffffffu, rsum, 2);
            if (tr == 0) atomicAdd(&rowsum[row], rsum);
        }
    }
    if (offdiag) {
#pragma unroll
        for (int nf = 0; nf < 8; nf++)
#pragma unroll
            for (int p = 0; p < 2; p++) {
                float v = csum[nf][p];
                v += __shfl_xor_sync(0xffffffffu, v, 4);
                v += __shfl_xor_sync(0xffffffffu, v, 8);
                v += __shfl_xor_sync(0xffffffffu, v, 16);
                if (lane < 4) atomicAdd(&colsum[wn * 64 + nf * 8 + lane * 2 + p], v);
            }
    }
    __syncthreads();
    for (int t = tid; t < 128; t += 256) {
        atomicAdd(&g_negsum[m0 + t], rowsum[t]);
        if (offdiag) atomicAdd(&g_negsum[n0 + t], colsum[t]);
    }
}

// ---------------------------------------------------------------------------
// K2: positive-pair loss from precomputed per-class dist table
// ---------------------------------------------------------------------------
__global__ __launch_bounds__(256) void k_pairs2() {
    __shared__ float ns[CMAX];
    __shared__ float wsum[8];
    const int c = blockIdx.x, tid = threadIdx.x;
    int cnt = g_count[c];
    if (cnt > CMAX) cnt = CMAX;
    for (int t = tid; t < cnt; t += 256)
        ns[t] = g_negsum[g_members[c * CMAX + t]];
    __syncthreads();
    float acc = 0.f;
    for (int a = tid; a < cnt; a += 256) {
        float na = ns[a];
        const float* pd = &g_pd[(c * CMAX + a) * CMAX];
        for (int b = a + 1; b < cnt; b++) {
            float J = logf(na + ns[b]) + pd[b];
            float h = fmaxf(J, 0.f);
            acc += h * h;
        }
    }
#pragma unroll
    for (int o = 16; o; o >>= 1) acc += __shfl_xor_sync(0xffffffffu, acc, o);
    if ((tid & 31) == 0) wsum[tid >> 5] = acc;
    __syncthreads();
    if (tid == 0) {
        float s = 0.f;
#pragma unroll
        for (int w = 0; w < 8; w++) s += wsum[w];
        atomicAdd(&g_loss, s);
    }
}

// ---------------------------------------------------------------------------
// K3: finalize
// ---------------------------------------------------------------------------
__global__ void k_final(float* __restrict__ out) {
    float lp = 0.f;
    for (int c = 0; c < NCLS; c++) {
        float cc = (float)g_count[c];
        lp += cc * (cc - 1.f);
    }
    out[0] = g_loss / lp;
}

// ---------------------------------------------------------------------------
extern "C" void kernel_launch(void* const* d_in, const int* in_sizes, int n_in,
                              void* d_out, int out_size) {
    const void *Xp, *Tp;
    if (in_sizes[0] == NN * DD) { Xp = d_in[0]; Tp = d_in[1]; }
    else                        { Xp = d_in[1]; Tp = d_in[0]; }
    const float* X = (const float*)Xp;
    float* out = (float*)d_out;

    // not stream-ordered; safe under graph capture, idempotent
    cudaFuncSetAttribute(k_gemm_mma, cudaFuncAttributeMaxDynamicSharedMemorySize,
                         SMEM_DYN);

    k_cvt<<<1, 1024>>>((const int*)Tp);
    k_sq_split<<<NN / 8, 256>>>(X);
    k_gemm_mma<<<NTRI, 256, SMEM_DYN>>>();
    k_pairs2<<<NCLS, 256>>>();
    k_final<<<1, 1>>>(out);
}

// round 9
// speedup vs baseline: 3.6071x; 1.1035x over previous
#include <cuda_runtime.h>
#include <cuda_bf16.h>
#include <cstdint>

#define NN 4096
#define DD 512
#define NCLS 64
#define CMAX 160
#define NTRI 528            // 32*33/2 upper-tri 128x128 tiles

// ---------------- device globals (scratch; no runtime alloc) ----------------
__device__ int   g_tgt[NN];
__device__ int   g_rank[NN];
__device__ int   g_members[NCLS * CMAX];
__device__ int   g_count[NCLS];
__device__ float g_sq[NN];
__device__ float g_negsum[NN];
__device__ float g_loss;
__device__ float g_pd[NCLS * CMAX * CMAX];   // dist for same-class pairs (ri<rj)
__device__ uint4 g_hi4[NN * DD / 8];         // bf16 hi split, row-major (64 uint4/row)
__device__ uint4 g_lo4[NN * DD / 8];         // bf16 lo split

// ---------------- PTX helpers ----------------
__device__ __forceinline__ uint32_t s2u(const void* p) {
    uint32_t a;
    asm("{ .reg .u64 t; cvta.to.shared.u64 t, %1; cvt.u32.u64 %0, t; }"
        : "=r"(a) : "l"(p));
    return a;
}
__device__ __forceinline__ void cp16(uint32_t saddr, const void* g) {
    asm volatile("cp.async.cg.shared.global [%0], [%1], 16;" :: "r"(saddr), "l"(g));
}
#define CP_COMMIT() asm volatile("cp.async.commit_group;" ::: "memory")
#define CP_WAIT0()  asm volatile("cp.async.wait_group 0;" ::: "memory")

__device__ __forceinline__ void ldm_x4(uint32_t& r0, uint32_t& r1, uint32_t& r2,
                                       uint32_t& r3, uint32_t a) {
    asm volatile("ldmatrix.sync.aligned.m8n8.x4.shared.b16 {%0,%1,%2,%3}, [%4];"
                 : "=r"(r0), "=r"(r1), "=r"(r2), "=r"(r3) : "r"(a));
}
__device__ __forceinline__ void mma16816(float* d, const uint32_t* a, const uint32_t* b) {
    asm volatile(
        "mma.sync.aligned.m16n8k16.row.col.f32.bf16.bf16.f32 "
        "{%0,%1,%2,%3}, {%4,%5,%6,%7}, {%8,%9}, {%0,%1,%2,%3};"
        : "+f"(d[0]), "+f"(d[1]), "+f"(d[2]), "+f"(d[3])
        : "r"(a[0]), "r"(a[1]), "r"(a[2]), "r"(a[3]), "r"(b[0]), "r"(b[1]));
}

// ---------------- fast math (no MUFU on hot path) ----------------
__device__ __forceinline__ float fast_dist(float d2) {
    float y = __int_as_float(0x5f3759dfu - (__float_as_uint(d2) >> 1));
    y = y * fmaf(-0.5f * d2, y * y, 1.5f);
    y = y * fmaf(-0.5f * d2, y * y, 1.5f);
    y = y * fmaf(-0.5f * d2, y * y, 1.5f);
    return d2 > 1e-18f ? d2 * y : 0.0f;
}
__device__ __forceinline__ float exp1m(float dist) {  // exp(1 - dist)
    float t = (1.0f - dist) * 1.4426950408889634f;
    t = fmaxf(t, -125.0f);
    int n = __float2int_rn(t);
    float f = t - (float)n;
    float p = 1.3333558146e-3f;
    p = fmaf(p, f, 9.6181291076e-3f);
    p = fmaf(p, f, 5.5504108664e-2f);
    p = fmaf(p, f, 2.4022650696e-1f);
    p = fmaf(p, f, 6.9314718056e-1f);
    p = fmaf(p, f, 1.0f);
    return __int_as_float((uint32_t)(n + 127) << 23) * p;
}

// ---------------------------------------------------------------------------
// K-1: dtype-normalize targets (int32 or int64). One block, trivial.
// ---------------------------------------------------------------------------
__global__ __launch_bounds__(1024) void k_cvt(const int* __restrict__ t) {
    __shared__ int any_odd;
    int tid = threadIdx.x;
    if (tid == 0) any_odd = 0;
    __syncthreads();
    int local = 0;
    for (int i = tid; i < NN / 2; i += 1024) local |= t[2 * i + 1];
    if (local) atomicOr(&any_odd, 1);
    __syncthreads();
    bool is64 = (any_odd == 0);
    for (int i = tid; i < NN; i += 1024) g_tgt[i] = is64 ? t[2 * i] : t[i];
}

// ---------------------------------------------------------------------------
// K-0.5: per-class rank/members via block-wide ballot prefix scan.
// One block per class; 16 rounds of 256 coalesced loads.
// ---------------------------------------------------------------------------
__global__ __launch_bounds__(256) void k_rank() {
    const int c = blockIdx.x, tid = threadIdx.x;
    const int wid = tid >> 5, lane = tid & 31;
    __shared__ int wtot[8], wpre[8];
    __shared__ int base;
    if (tid == 0) base = 0;
    __syncthreads();
    for (int r0 = 0; r0 < NN; r0 += 256) {
        int i = r0 + tid;
        bool f = (g_tgt[i] == c);
        unsigned m = __ballot_sync(0xffffffffu, f);
        int myoff = __popc(m & ((1u << lane) - 1u));
        if (lane == 0) wtot[wid] = __popc(m);
        __syncthreads();
        if (tid < 8) {
            int s = 0;
            for (int w = 0; w < tid; w++) s += wtot[w];
            wpre[tid] = s;
        }
        __syncthreads();
        if (f) {
            int rk = base + wpre[wid] + myoff;
            g_rank[i] = rk;
            if (rk < CMAX) g_members[c * CMAX + rk] = i;
        }
        __syncthreads();
        if (tid == 0) {
            int s = 0;
            for (int w = 0; w < 8; w++) s += wtot[w];
            base += s;
        }
        __syncthreads();
    }
    if (tid == 0) g_count[c] = base;
}

// ---------------------------------------------------------------------------
// K0: row norms + bf16 hi/lo split + zero accumulators
// ---------------------------------------------------------------------------
__global__ __launch_bounds__(256) void k_sq_split(const float* __restrict__ X) {
    int warp = threadIdx.x >> 5, lane = threadIdx.x & 31;
    int row = blockIdx.x * 8 + warp;
    const float4* xr = (const float4*)(X + (size_t)row * DD);
    uint2* hi2 = (uint2*)g_hi4;
    uint2* lo2 = (uint2*)g_lo4;
    float s = 0.f;
#pragma unroll
    for (int q = 0; q < 4; q++) {
        int i4 = lane + q * 32;
        float4 v = xr[i4];
        s += v.x * v.x + v.y * v.y + v.z * v.z + v.w * v.w;
        union { __nv_bfloat16 b[4]; uint2 u; } H, L;
        H.b[0] = __float2bfloat16(v.x); H.b[1] = __float2bfloat16(v.y);
        H.b[2] = __float2bfloat16(v.z); H.b[3] = __float2bfloat16(v.w);
        L.b[0] = __float2bfloat16(v.x - __bfloat162float(H.b[0]));
        L.b[1] = __float2bfloat16(v.y - __bfloat162float(H.b[1]));
        L.b[2] = __float2bfloat16(v.z - __bfloat162float(H.b[2]));
        L.b[3] = __float2bfloat16(v.w - __bfloat162float(H.b[3]));
        hi2[(size_t)row * 128 + i4] = H.u;
        lo2[(size_t)row * 128 + i4] = L.u;
    }
#pragma unroll
    for (int o = 16; o; o >>= 1) s += __shfl_xor_sync(0xffffffffu, s, o);
    if (lane == 0) { g_sq[row] = s; g_negsum[row] = 0.f; }
    if (blockIdx.x == 0 && threadIdx.x == 0) g_loss = 0.f;
}

// ---------------------------------------------------------------------------
// K1: split-bf16 symmetric GEMM via ldmatrix + mma.sync (HMMA), fused epilogue.
// 528 upper-tri 128x128 tiles, BK=64 double-buffered cp.async, 8 warps 32x64.
// ---------------------------------------------------------------------------
#define BUFSZ 16384               // one operand chunk: 128 rows x 128B
#define PHSZ  (4 * BUFSZ)         // Ahi,Alo,Bhi,Blo
#define SMEM_DYN (2 * PHSZ)       // double buffered: 128 KB

__device__ __forceinline__ void load_chunk(uint32_t dynb, int stage, int m0, int n0,
                                           int kq, int tid) {
#pragma unroll
    for (int op = 0; op < 4; op++) {
        const uint4* src = (op & 1) ? g_lo4 : g_hi4;
        int rb = (op < 2) ? m0 : n0;
        uint32_t dst = dynb + stage * PHSZ + op * BUFSZ;
#pragma unroll
        for (int u = 0; u < 4; u++) {
            int f = tid + u * 256;                 // 0..1023
            int r = f >> 3, c8 = f & 7;
            uint32_t bo = (uint32_t)(r * 128 + c8 * 16);
            cp16(dst + (bo ^ ((bo >> 3) & 0x70)),
                 &src[(size_t)(rb + r) * 64 + kq + c8]);
        }
    }
}

__global__ __launch_bounds__(256) void k_gemm_mma() {
    extern __shared__ __align__(1024) char dyn[];
    __shared__ int   tR[128], tC[128], rkR[128], rkC[128];
    __shared__ float sqR[128], sqC[128], rowsum[128], colsum[128];

    const int tid = threadIdx.x;
    const int lane = tid & 31;
    const int wid = tid >> 5;
    const int wm = wid & 3, wn = wid >> 2;
    const uint32_t dynb = s2u(dyn);

    // upper-tri tile decode: blk = bj*(bj+1)/2 + bi, bi<=bj
    int k = blockIdx.x;
    int bj = (int)((sqrtf(8.f * (float)k + 1.f) - 1.f) * 0.5f);
    while ((bj + 1) * (bj + 2) / 2 <= k) bj++;
    while (bj * (bj + 1) / 2 > k) bj--;
    int bi = k - bj * (bj + 1) / 2;
    const int m0 = bi * 128, n0 = bj * 128;
    const bool offdiag = (bi != bj);

    for (int t = tid; t < 128; t += 256) {
        tR[t] = g_tgt[m0 + t];   tC[t] = g_tgt[n0 + t];
        sqR[t] = g_sq[m0 + t];   sqC[t] = g_sq[n0 + t];
        rkR[t] = g_rank[m0 + t]; rkC[t] = g_rank[n0 + t];
        rowsum[t] = 0.f;         colsum[t] = 0.f;
    }

    float acc[2][8][4];
#pragma unroll
    for (int mi = 0; mi < 2; mi++)
#pragma unroll
        for (int nf = 0; nf < 8; nf++)
#pragma unroll
            for (int e = 0; e < 4; e++) acc[mi][nf][e] = 0.f;

    load_chunk(dynb, 0, m0, n0, 0, tid);
    CP_COMMIT(); CP_WAIT0();
    __syncthreads();

    const int mat = lane >> 3, rr = lane & 7;

    for (int ci = 0; ci < 8; ci++) {
        const int cur = ci & 1;
        if (ci < 7) { load_chunk(dynb, cur ^ 1, m0, n0, (ci + 1) * 8, tid); CP_COMMIT(); }

        const uint32_t Ah = dynb + cur * PHSZ;
        const uint32_t Al = Ah + BUFSZ;
        const uint32_t Bh = Ah + 2 * BUFSZ;
        const uint32_t Bl = Ah + 3 * BUFSZ;

#pragma unroll
        for (int ks = 0; ks < 4; ks++) {
            uint32_t ahi[2][4], alo[2][4];
#pragma unroll
            for (int mi = 0; mi < 2; mi++) {
                int row = wm * 32 + mi * 16 + (mat & 1) * 8 + rr;
                uint32_t bo = (uint32_t)(row * 128 + ks * 32 + (mat >> 1) * 16);
                uint32_t sw = bo ^ ((bo >> 3) & 0x70);
                ldm_x4(ahi[mi][0], ahi[mi][1], ahi[mi][2], ahi[mi][3], Ah + sw);
                ldm_x4(alo[mi][0], alo[mi][1], alo[mi][2], alo[mi][3], Al + sw);
            }
            uint32_t bhi[8][2], blo[8][2];
#pragma unroll
            for (int q = 0; q < 4; q++) {
                int row = wn * 64 + q * 16 + (mat >> 1) * 8 + rr;
                uint32_t bo = (uint32_t)(row * 128 + ks * 32 + (mat & 1) * 16);
                uint32_t sw = bo ^ ((bo >> 3) & 0x70);
                uint32_t r0, r1, r2, r3;
                ldm_x4(r0, r1, r2, r3, Bh + sw);
                bhi[2 * q][0] = r0; bhi[2 * q][1] = r1;
                bhi[2 * q + 1][0] = r2; bhi[2 * q + 1][1] = r3;
                ldm_x4(r0, r1, r2, r3, Bl + sw);
                blo[2 * q][0] = r0; blo[2 * q][1] = r1;
                blo[2 * q + 1][0] = r2; blo[2 * q + 1][1] = r3;
            }
#pragma unroll
            for (int mi = 0; mi < 2; mi++)
#pragma unroll
                for (int nf = 0; nf < 8; nf++) {
                    mma16816(acc[mi][nf], ahi[mi], bhi[nf]);
                    mma16816(acc[mi][nf], ahi[mi], blo[nf]);
                    mma16816(acc[mi][nf], alo[mi], bhi[nf]);
                }
        }
        if (ci < 7) CP_WAIT0();
        __syncthreads();
    }

    // ---- epilogue: dist, masked exp, row/col negsums, pos-pair dist store ----
    const int tq = lane >> 2, tr = lane & 3;
    float csum[8][2];
#pragma unroll
    for (int nf = 0; nf < 8; nf++) { csum[nf][0] = 0.f; csum[nf][1] = 0.f; }

#pragma unroll
    for (int mi = 0; mi < 2; mi++) {
#pragma unroll
        for (int h = 0; h < 2; h++) {
            int row = wm * 32 + mi * 16 + tq + h * 8;
            int ti = tR[row]; float si = sqR[row]; int ri = rkR[row];
            int gi = m0 + row;
            float rsum = 0.f;
#pragma unroll
            for (int nf = 0; nf < 8; nf++) {
#pragma unroll
                for (int p = 0; p < 2; p++) {
                    int col = wn * 64 + nf * 8 + tr * 2 + p;
                    float dot = acc[mi][nf][h * 2 + p];
                    float d2 = fmaxf(si + sqC[col] - 2.f * dot, 0.f);
                    float dist = fast_dist(d2);
                    bool same = (ti == tC[col]);
                    float ev = same ? 0.f : exp1m(dist);
                    rsum += ev;
                    csum[nf][p] += ev;
                    if (same) {
                        int gj = n0 + col;
                        if (gi < gj) {
                            int rj = rkC[col];
                            if (ri < CMAX && rj < CMAX)
                                g_pd[(ti * CMAX + ri) * CMAX + rj] = dist;
                        }
                    }
                }
            }
            rsum += __shfl_xor_sync(0xffffffffu, rsum, 1);
            rsum += __shfl_xor_sync(0xffffffffu, rsum, 2);
            if (tr == 0) atomicAdd(&rowsum[row], rsum);
        }
    }
    if (offdiag) {
#pragma unroll
        for (int nf = 0; nf < 8; nf++)
#pragma unroll
            for (int p = 0; p < 2; p++) {
                float v = csum[nf][p];
                v += __shfl_xor_sync(0xffffffffu, v, 4);
                v += __shfl_xor_sync(0xffffffffu, v, 8);
                v += __shfl_xor_sync(0xffffffffu, v, 16);
                if (lane < 4) atomicAdd(&colsum[wn * 64 + nf * 8 + lane * 2 + p], v);
            }
    }
    __syncthreads();
    for (int t = tid; t < 128; t += 256) {
        atomicAdd(&g_negsum[m0 + t], rowsum[t]);
        if (offdiag) atomicAdd(&g_negsum[n0 + t], colsum[t]);
    }
}

// ---------------------------------------------------------------------------
// K2: positive-pair loss. Thread-per-pair flattened triangular decode.
// ---------------------------------------------------------------------------
__global__ __launch_bounds__(256) void k_pairs2() {
    __shared__ float ns[CMAX];
    __shared__ float wsum[8];
    const int c = blockIdx.x, tid = threadIdx.x;
    int cnt = g_count[c];
    if (cnt > CMAX) cnt = CMAX;
    for (int t = tid; t < cnt; t += 256)
        ns[t] = g_negsum[g_members[c * CMAX + t]];
    __syncthreads();

    const int P = cnt * (cnt - 1) / 2;
    float acc = 0.f;
    for (int p = tid; p < P; p += 256) {
        // decode pair index p -> (a,b), a<b, a-major ordering:
        // idx(a,b) = a*cnt - a(a+1)/2 + (b-a-1)
        float fn = (float)cnt;
        float disc = (2.f * fn - 1.f) * (2.f * fn - 1.f) - 8.f * (float)p;
        int a = (int)((2.f * fn - 1.f - sqrtf(fmaxf(disc, 0.f))) * 0.5f);
        if (a < 0) a = 0;
        while (a > 0 && a * cnt - a * (a + 1) / 2 > p) a--;
        while ((a + 1) * cnt - (a + 1) * (a + 2) / 2 <= p) a++;
        int b = p - (a * cnt - a * (a + 1) / 2) + a + 1;
        float J = __logf(ns[a] + ns[b]) + g_pd[(c * CMAX + a) * CMAX + b];
        float h = fmaxf(J, 0.f);
        acc += h * h;
    }
#pragma unroll
    for (int o = 16; o; o >>= 1) acc += __shfl_xor_sync(0xffffffffu, acc, o);
    if ((tid & 31) == 0) wsum[tid >> 5] = acc;
    __syncthreads();
    if (tid == 0) {
        float s = 0.f;
#pragma unroll
        for (int w = 0; w < 8; w++) s += wsum[w];
        atomicAdd(&g_loss, s);
    }
}

// ---------------------------------------------------------------------------
// K3: finalize
// ---------------------------------------------------------------------------
__global__ void k_final(float* __restrict__ out) {
    float lp = 0.f;
    for (int c = 0; c < NCLS; c++) {
        float cc = (float)g_count[c];
        lp += cc * (cc - 1.f);
    }
    out[0] = g_loss / lp;
}

// ---------------------------------------------------------------------------
extern "C" void kernel_launch(void* const* d_in, const int* in_sizes, int n_in,
                              void* d_out, int out_size) {
    const void *Xp, *Tp;
    if (in_sizes[0] == NN * DD) { Xp = d_in[0]; Tp = d_in[1]; }
    else                        { Xp = d_in[1]; Tp = d_in[0]; }
    const float* X = (const float*)Xp;
    float* out = (float*)d_out;

    // not stream-ordered; safe under graph capture, idempotent
    cudaFuncSetAttribute(k_gemm_mma, cudaFuncAttributeMaxDynamicSharedMemorySize,
                         SMEM_DYN);

    k_cvt<<<1, 1024>>>((const int*)Tp);
    k_rank<<<NCLS, 256>>>();
    k_sq_split<<<NN / 8, 256>>>(X);
    k_gemm_mma<<<NTRI, 256, SMEM_DYN>>>();
    k_pairs2<<<NCLS, 256>>>();
    k_final<<<1, 1>>>(out);
}